// round 11
// baseline (speedup 1.0000x reference)
#include <cuda_runtime.h>
#include <cstdint>
#include <cstddef>

#define B 2048

// ---- global scratch (static device allocations are permitted) ----
__device__ float gX[B * 132];          // input vectors  [e][132] (131 used)
__device__ float gH[4][B * 128];       // activations h1..h4
__device__ float gU[2][B * 128];       // backward ping-pong
__device__ float gWT[3][128 * 128];    // Wh[l] transposed: gWT[l][k*128+t] = Wh[l][t*128+k]
__device__ float gWiT[128 * 132];      // Wi transposed:    gWiT[t*132+j]   = Wi[j*128+t]
__device__ float gS[B], gC[B], gXs[B], gVal[B];

// ---------------------------------------------------------------------------
// K_tr: one-shot weight transposes
// ---------------------------------------------------------------------------
__global__ void k_tr(const float* __restrict__ Wh, const float* __restrict__ Wi)
{
    int gt = blockIdx.x * 256 + threadIdx.x;
    if (gt < 3 * 16384) {
        int l = gt >> 14, r = gt & 16383, t = r >> 7, k = r & 127;
        gWT[l][k * 128 + t] = Wh[gt];
    } else {
        int g2 = gt - 3 * 16384;
        if (g2 < 131 * 128) {
            int j = g2 >> 7, t = g2 & 127;
            gWiT[t * 132 + j] = Wi[g2];
        }
    }
}

// ---------------------------------------------------------------------------
// K_front: gather/reparam front-end; builds gX; writes fmean/flog/d2c/d2o
// grid 1024 x 256: one thread per (e, k)
// ---------------------------------------------------------------------------
__global__ void k_front(const float* __restrict__ centers,
                        const float* __restrict__ eps,
                        const float* __restrict__ dk,
                        const void* __restrict__ pA2048, const void* __restrict__ pB2048,
                        float* __restrict__ o_fmean, float* __restrict__ o_flog,
                        float* __restrict__ o_d2c, float* __restrict__ o_d2o)
{
    int gt = blockIdx.x * 256 + threadIdx.x;
    int e = gt >> 7, k = gt & 127;

    const unsigned* ua = (const unsigned*)pA2048;
    bool ai = true;
#pragma unroll
    for (int i = 0; i < 8; i++) ai &= (ua[i] < 1000u);
    const int*   idxp = (const int*)(ai ? pA2048 : pB2048);
    const float* xsp  = (const float*)(ai ? pB2048 : pA2048);

    int id = idxp[e];
    float m  = dk[id * 256 + k];
    float ls = dk[id * 256 + 128 + k];
    float ep = eps[id * 128 + k];
    float ft = fmaf(expf(0.5f * ls), ep, m);
    __stcs(o_fmean + (size_t)e * 128 + k, m);
    __stcs(o_flog  + (size_t)e * 128 + k, ls);

    if (k == 0) {
        float s = 1e-10f + expf(-ft);
        float c = centers[e * 4];
        gS[e] = s; gC[e] = c; gXs[e] = xsp[e];
        gX[e * 132] = c * s;
    } else {
        gX[e * 132 + 3 + k] = ft;                       // rows 4..130
        if (k <= 3) gX[e * 132 + k] = centers[e * 4 + k]; // rows 1..3
        if (k >= 2 && k <= 10) o_d2o[(size_t)e * 9 + (k - 2)] = 0.f;
        if (k == 11) o_d2c[e] = 0.f;
    }
}

// ---------------------------------------------------------------------------
// K_fwd<KD,PITCH,BMODE>: Aout[e][t] = relu(sum_k Ain[e][k] * W[k*128+t] + bias[t])
// block 128 (t = neuron), 4 examples per block, grid 512. Barrier-free stream.
// Also emits a grid-stride __stcs zero-fill chunk of d2f.
// ---------------------------------------------------------------------------
template <int KD, int PITCH, int BMODE>
__global__ void __launch_bounds__(128) k_fwd(
    const float* __restrict__ W,
    const float* __restrict__ biasA, const float* __restrict__ biasB,
    const float* __restrict__ Ain, float* __restrict__ Aout,
    float* __restrict__ o_d2f, int ze0, int zn4)
{
    __shared__ float As[4 * 132];
    const int t = threadIdx.x;
    const int e0 = blockIdx.x * 4;

    const float* src = Ain + (size_t)e0 * PITCH;
    for (int i = t; i < 4 * PITCH; i += 128)
        As[(i / PITCH) * 132 + (i % PITCH)] = src[i];

    // zero-fill chunk (streaming stores; skip each example-row's first float4)
    {
        float4 z = make_float4(0.f, 0.f, 0.f, 0.f);
        float4* zb = (float4*)(o_d2f + (size_t)ze0 * 16384);
        for (int i = blockIdx.x * 128 + t; i < zn4; i += 512 * 128)
            if (i & 4095) __stcs(zb + i, z);
    }
    __syncthreads();

    float bv;
    if (BMODE == 0) {
        bool a_bi = true;
#pragma unroll
        for (int i = 0; i < 8; i++) a_bi &= (biasA[i] == 0.f);
        bv = a_bi ? biasA[t] : biasB[t];
    } else {
        bv = biasA[t];
    }
    float a0 = bv, a1 = bv, a2 = bv, a3 = bv;

#pragma unroll 4
    for (int k = 0; k + 3 < KD; k += 4) {
        float w0 = __ldg(W + (k + 0) * 128 + t);
        float w1 = __ldg(W + (k + 1) * 128 + t);
        float w2 = __ldg(W + (k + 2) * 128 + t);
        float w3 = __ldg(W + (k + 3) * 128 + t);
        {   float4 v = *(const float4*)(As + 0 * 132 + k);
            a0 = fmaf(w0, v.x, a0); a0 = fmaf(w1, v.y, a0);
            a0 = fmaf(w2, v.z, a0); a0 = fmaf(w3, v.w, a0); }
        {   float4 v = *(const float4*)(As + 1 * 132 + k);
            a1 = fmaf(w0, v.x, a1); a1 = fmaf(w1, v.y, a1);
            a1 = fmaf(w2, v.z, a1); a1 = fmaf(w3, v.w, a1); }
        {   float4 v = *(const float4*)(As + 2 * 132 + k);
            a2 = fmaf(w0, v.x, a2); a2 = fmaf(w1, v.y, a2);
            a2 = fmaf(w2, v.z, a2); a2 = fmaf(w3, v.w, a2); }
        {   float4 v = *(const float4*)(As + 3 * 132 + k);
            a3 = fmaf(w0, v.x, a3); a3 = fmaf(w1, v.y, a3);
            a3 = fmaf(w2, v.z, a3); a3 = fmaf(w3, v.w, a3); }
    }
#pragma unroll
    for (int k = (KD / 4) * 4; k < KD; k++) {
        float w = __ldg(W + k * 128 + t);
        a0 = fmaf(w, As[0 * 132 + k], a0);
        a1 = fmaf(w, As[1 * 132 + k], a1);
        a2 = fmaf(w, As[2 * 132 + k], a2);
        a3 = fmaf(w, As[3 * 132 + k], a3);
    }
    float* dst = Aout + (size_t)e0 * 128;
    dst[t]       = fmaxf(a0, 0.f);
    dst[128 + t] = fmaxf(a1, 0.f);
    dst[256 + t] = fmaxf(a2, 0.f);
    dst[384 + t] = fmaxf(a3, 0.f);
}

// ---------------------------------------------------------------------------
// K_val: val[e] = h4[e] . Wf + bf ; u4[e][t] = (h4>0) ? Wf[t] : 0
// ---------------------------------------------------------------------------
__global__ void __launch_bounds__(256) k_val(
    const float* __restrict__ pA128, const float* __restrict__ pB128,
    const float* __restrict__ bf)
{
    bool a_bi = true;
#pragma unroll
    for (int i = 0; i < 8; i++) a_bi &= (pA128[i] == 0.f);
    const float* Wf = a_bi ? pB128 : pA128;

    int tid = threadIdx.x;
    int w = tid >> 5, lane = tid & 31;
    int e = blockIdx.x * 8 + w;
    const float* h4 = gH[3] + (size_t)e * 128;
    float4 hv = *(const float4*)(h4 + lane * 4);
    float4 wv = *(const float4*)(Wf + lane * 4);
    float p = hv.x * wv.x + hv.y * wv.y + hv.z * wv.z + hv.w * wv.w;
#pragma unroll
    for (int o = 16; o > 0; o >>= 1) p += __shfl_down_sync(0xffffffffu, p, o);
    if (lane == 0) gVal[e] = p + bf[0];

    for (int i = tid; i < 8 * 128; i += 256) {
        int el = i >> 7, t = i & 127;
        size_t off = (size_t)(blockIdx.x * 8 + el) * 128 + t;
        float h = gH[3][off];
        gU[0][off] = (h > 0.f) ? Wf[t] : 0.f;
    }
}

// ---------------------------------------------------------------------------
// K_bwd: Uout[e][t] = (Hm[e][t]>0) * sum_k WT[k*128+t] * Uin[e][k]
// (WT is the transposed layer weight -> column-coalesced reads)
// ---------------------------------------------------------------------------
__global__ void __launch_bounds__(128) k_bwd(
    const float* __restrict__ WT, const float* __restrict__ Uin,
    const float* __restrict__ Hm, float* __restrict__ Uout,
    float* __restrict__ o_d2f, int ze0, int zn4)
{
    __shared__ float Us[4 * 128];
    const int t = threadIdx.x;
    const int e0 = blockIdx.x * 4;

    const float* src = Uin + (size_t)e0 * 128;
    for (int i = t; i < 512; i += 128) Us[i] = src[i];
    {
        float4 z = make_float4(0.f, 0.f, 0.f, 0.f);
        float4* zb = (float4*)(o_d2f + (size_t)ze0 * 16384);
        for (int i = blockIdx.x * 128 + t; i < zn4; i += 512 * 128)
            if (i & 4095) __stcs(zb + i, z);
    }
    __syncthreads();

    float a0 = 0.f, a1 = 0.f, a2 = 0.f, a3 = 0.f;
#pragma unroll 4
    for (int k = 0; k < 128; k += 4) {
        float w0 = __ldg(WT + (k + 0) * 128 + t);
        float w1 = __ldg(WT + (k + 1) * 128 + t);
        float w2 = __ldg(WT + (k + 2) * 128 + t);
        float w3 = __ldg(WT + (k + 3) * 128 + t);
        {   float4 v = *(const float4*)(Us + 0 * 128 + k);
            a0 = fmaf(w0, v.x, a0); a0 = fmaf(w1, v.y, a0);
            a0 = fmaf(w2, v.z, a0); a0 = fmaf(w3, v.w, a0); }
        {   float4 v = *(const float4*)(Us + 1 * 128 + k);
            a1 = fmaf(w0, v.x, a1); a1 = fmaf(w1, v.y, a1);
            a1 = fmaf(w2, v.z, a1); a1 = fmaf(w3, v.w, a1); }
        {   float4 v = *(const float4*)(Us + 2 * 128 + k);
            a2 = fmaf(w0, v.x, a2); a2 = fmaf(w1, v.y, a2);
            a2 = fmaf(w2, v.z, a2); a2 = fmaf(w3, v.w, a2); }
        {   float4 v = *(const float4*)(Us + 3 * 128 + k);
            a3 = fmaf(w0, v.x, a3); a3 = fmaf(w1, v.y, a3);
            a3 = fmaf(w2, v.z, a3); a3 = fmaf(w3, v.w, a3); }
    }
    const float* hm = Hm + (size_t)e0 * 128;
    float* dst = Uout + (size_t)e0 * 128;
    dst[t]       = (hm[t]       > 0.f) ? a0 : 0.f;
    dst[128 + t] = (hm[128 + t] > 0.f) ? a1 : 0.f;
    dst[256 + t] = (hm[256 + t] > 0.f) ? a2 : 0.f;
    dst[384 + t] = (hm[384 + t] > 0.f) ? a3 : 0.f;
}

// ---------------------------------------------------------------------------
// K_fin: g[e][j] = sum_t WiT[t*132+j] * u1[e][t]; scatter all scalar outputs.
// block 160 (j = tid < 131), 4 examples/block, grid 512.
// ---------------------------------------------------------------------------
__global__ void __launch_bounds__(160) k_fin(
    float* __restrict__ o_res, float* __restrict__ o_coeffs,
    float* __restrict__ o_d1c, float* __restrict__ o_d1o,
    float* __restrict__ o_d1f, float* __restrict__ o_d2f)
{
    __shared__ float Us[4 * 128];
    const int tid = threadIdx.x;
    const int e0 = blockIdx.x * 4;
    const float* src = gU[1] + (size_t)e0 * 128;
    for (int i = tid; i < 512; i += 160) Us[i] = src[i];
    __syncthreads();

    int j = tid;
    if (j >= 131) return;

    float g0 = 0.f, g1 = 0.f, g2 = 0.f, g3 = 0.f;
#pragma unroll 4
    for (int t = 0; t < 128; t += 4) {
        float w0 = __ldg(gWiT + (t + 0) * 132 + j);
        float w1 = __ldg(gWiT + (t + 1) * 132 + j);
        float w2 = __ldg(gWiT + (t + 2) * 132 + j);
        float w3 = __ldg(gWiT + (t + 3) * 132 + j);
        {   float4 v = *(const float4*)(Us + 0 * 128 + t);
            g0 = fmaf(w0, v.x, g0); g0 = fmaf(w1, v.y, g0);
            g0 = fmaf(w2, v.z, g0); g0 = fmaf(w3, v.w, g0); }
        {   float4 v = *(const float4*)(Us + 1 * 128 + t);
            g1 = fmaf(w0, v.x, g1); g1 = fmaf(w1, v.y, g1);
            g1 = fmaf(w2, v.z, g1); g1 = fmaf(w3, v.w, g1); }
        {   float4 v = *(const float4*)(Us + 2 * 128 + t);
            g2 = fmaf(w0, v.x, g2); g2 = fmaf(w1, v.y, g2);
            g2 = fmaf(w2, v.z, g2); g2 = fmaf(w3, v.w, g2); }
        {   float4 v = *(const float4*)(Us + 3 * 128 + t);
            g3 = fmaf(w0, v.x, g3); g3 = fmaf(w1, v.y, g3);
            g3 = fmaf(w2, v.z, g3); g3 = fmaf(w3, v.w, g3); }
    }
    float g[4] = {g0, g1, g2, g3};

#pragma unroll
    for (int e = 0; e < 4; e++) {
        int gb = e0 + e;
        if (j >= 4) {
            o_d1f[(size_t)gb * 128 + (j - 3)] = g[e];
        } else if (j == 0) {
            float s = gS[gb], c = gC[gb], val = gVal[gb];
            float gg = g[e];
            float d1c = gg * s;
            float h00 = gg * c * (s - 1e-10f);          // g0 * c * exp(-ft0)
            o_d1c[gb] = d1c;
            o_coeffs[gb] = val;
            o_res[gb] = fmaf(d1c, gXs[gb] - c, val);
            o_d1f[(size_t)gb * 128] = -h00;
            *(float4*)(o_d2f + (size_t)gb * 16384) = make_float4(h00, 0.f, 0.f, 0.f);
        } else {  // j = 1..3
            o_d1o[(size_t)gb * 3 + (j - 1)] = g[e];
        }
    }
}

// ---------------------------------------------------------------------------
extern "C" void kernel_launch(void* const* d_in, const int* in_sizes, int n_in,
                              void* d_out, int out_size)
{
    (void)out_size;
    const float *centers = 0, *eps = 0, *dk = 0, *Wi = 0, *Wh = 0, *bh = 0, *bf = 0;
    const void* p2048[2] = {0, 0};
    const float* p128[2] = {0, 0};
    int n2 = 0, n1 = 0;
    for (int i = 0; i < n_in; i++) {
        switch (in_sizes[i]) {
            case 8192:   centers = (const float*)d_in[i]; break;  // (2048,4)
            case 128000: eps     = (const float*)d_in[i]; break;  // (1000,128)
            case 256000: dk      = (const float*)d_in[i]; break;  // (1000,256)
            case 16768:  Wi      = (const float*)d_in[i]; break;  // (131,128)
            case 49152:  Wh      = (const float*)d_in[i]; break;  // (3,128,128)
            case 384:    bh      = (const float*)d_in[i]; break;  // (3,128)
            case 1:      bf      = (const float*)d_in[i]; break;  // (1,)
            case 2048:   if (n2 < 2) p2048[n2++] = d_in[i]; break; // indecies / xs
            case 128:    if (n1 < 2) p128[n1++] = (const float*)d_in[i]; break; // bi / Wf
            default: break;
        }
    }
    float* out = (float*)d_out;
    float* o_res    = out;
    float* o_fmean  = out + B;
    float* o_flog   = o_fmean + (size_t)B * 128;
    float* o_coeffs = o_flog + (size_t)B * 128;
    float* o_d1c    = o_coeffs + B;
    float* o_d2c    = o_d1c + B;
    float* o_d1o    = o_d2c + B;
    float* o_d2o    = o_d1o + (size_t)B * 3;
    float* o_d1f    = o_d2o + (size_t)B * 9;
    float* o_d2f    = o_d1f + (size_t)B * 128;

    // device pointers to scratch symbols (no allocation; just address queries done
    // implicitly by referencing the symbols inside kernels — only gX/gH/gU needed here)
    // k_fwd/k_bwd take them as plain pointers via cudaGetSymbolAddress-free trick:
    // we launch with pointers obtained from small helper kernels is overkill; instead
    // pass via static device-symbol-referencing kernels. Simpler: use the symbols
    // directly by taking their addresses in device code — but k_fwd is generic, so
    // we fetch addresses host-side (query only, no allocation).
    static float *pX = 0, *pH0 = 0, *pH1 = 0, *pH2 = 0, *pH3 = 0, *pU0 = 0, *pU1 = 0, *pWT = 0;
    if (!pX) {
        cudaGetSymbolAddress((void**)&pX,  gX);
        cudaGetSymbolAddress((void**)&pH0, gH);
        pH1 = pH0 + (size_t)B * 128;
        pH2 = pH1 + (size_t)B * 128;
        pH3 = pH2 + (size_t)B * 128;
        cudaGetSymbolAddress((void**)&pU0, gU);
        pU1 = pU0 + (size_t)B * 128;
        cudaGetSymbolAddress((void**)&pWT, gWT);
    }

    const int ZN = 293 * 4096;   // float4 count per fwd zero chunk
    const int ZN2 = 292 * 4096;  // per bwd zero chunk

    k_tr<<<258, 256>>>(Wh, Wi);
    k_front<<<1024, 256>>>(centers, eps, dk, p2048[0], p2048[1],
                           o_fmean, o_flog, o_d2c, o_d2o);
    k_fwd<131, 132, 0><<<512, 128>>>(Wi, p128[0], p128[1], pX, pH0, o_d2f, 0, ZN);
    k_fwd<128, 128, 1><<<512, 128>>>(Wh + 0 * 16384, bh + 0, 0, pH0, pH1, o_d2f, 293, ZN);
    k_fwd<128, 128, 1><<<512, 128>>>(Wh + 1 * 16384, bh + 128, 0, pH1, pH2, o_d2f, 586, ZN);
    k_fwd<128, 128, 1><<<512, 128>>>(Wh + 2 * 16384, bh + 256, 0, pH2, pH3, o_d2f, 879, ZN);
    k_val<<<256, 256>>>(p128[0], p128[1], bf);
    k_bwd<<<512, 128>>>(pWT + 2 * 16384, pU0, pH2, pU1, o_d2f, 1172, ZN2);
    k_bwd<<<512, 128>>>(pWT + 1 * 16384, pU1, pH1, pU0, o_d2f, 1464, ZN2);
    k_bwd<<<512, 128>>>(pWT + 0 * 16384, pU0, pH0, pU1, o_d2f, 1756, ZN2);
    k_fin<<<512, 160>>>(o_res, o_coeffs, o_d1c, o_d1o, o_d1f, o_d2f);
}

// round 13
// speedup vs baseline: 1.3828x; 1.3828x over previous
#include <cuda_runtime.h>
#include <cstdint>
#include <cstddef>

#define NTHR 256
#define TB 8
#define NCOMP 256
#define PITCH 132

// smem layout (floats)
// Ws   : 131*132 = 17292  staged weight tile
// Xst  : 131*8   = 1048   input vectors, TRANSPOSED [k][e]
// Hst  : 3*128*8 = 3072   activations h1..h3 (masks for backward; h4 not stored)
// Ua/Ub: 128*8 each       backward ping-pong, transposed
// valP : 8*4              per-warp val partials
#define WS_OFF    0
#define XST_OFF   17292
#define HST_OFF   18340
#define UA_OFF    21412
#define UB_OFF    22436
#define VALP_OFF  23460
#define SMALL_OFF 23492
#define SMEM_FLOATS (SMALL_OFF + 40)
#define SMEM_BYTES (SMEM_FLOATS * 4)

typedef unsigned long long u64;

__device__ __forceinline__ u64 pk2(float x, float y) {
    u64 r; asm("mov.b64 %0, {%1, %2};" : "=l"(r) : "f"(x), "f"(y)); return r;
}
__device__ __forceinline__ void upk2(u64 v, float& x, float& y) {
    asm("mov.b64 {%0, %1}, %2;" : "=f"(x), "=f"(y) : "l"(v));
}
__device__ __forceinline__ void ffma2(u64& d, u64 a, u64 b) {
    asm("fma.rn.f32x2 %0, %1, %2, %0;" : "+l"(d) : "l"(a), "l"(b));
}

__device__ __forceinline__ void stage_w(float* Ws, const float* __restrict__ g, int rows, int tid) {
    for (int i4 = tid; i4 < rows * 32; i4 += NTHR) {
        int r = i4 >> 5, c4 = (i4 & 31) << 2;
        *(float4*)(Ws + r * PITCH + c4) = *(const float4*)(g + r * 128 + c4);
    }
}

// zero one example's d2f row block (16384 floats), skipping the first float4
#define ZCHUNK(e_) do {                                                         \
    float4 z4 = make_float4(0.f, 0.f, 0.f, 0.f);                                \
    float4* dst_ = (float4*)(o_d2f + (size_t)(b0 + (e_)) * 16384);              \
    for (int i_ = 1 + tid; i_ < 4096; i_ += NTHR) __stcs(dst_ + i_, z4);        \
  } while (0)

// backward step (packed): u_out[t] = mask_lvl[t] * sum_k Ws[t][k] * u_in[k]
#define BACKSTEP(UIN, UOUT, LVL) do {                                           \
    u64 p0 = 0ULL, p1 = 0ULL;                                                   \
    _Pragma("unroll 8")                                                         \
    for (int k = 0; k < 128; k += 4) {                                          \
        float4 wv = *(const float4*)(Ws + t * PITCH + k);                       \
        {   u64 ww = pk2(wv.x, wv.x);                                           \
            float4 uv = *(const float4*)((UIN) + (k + 0) * 8 + bbase);          \
            ffma2(p0, ww, pk2(uv.x, uv.y)); ffma2(p1, ww, pk2(uv.z, uv.w)); }   \
        {   u64 ww = pk2(wv.y, wv.y);                                           \
            float4 uv = *(const float4*)((UIN) + (k + 1) * 8 + bbase);          \
            ffma2(p0, ww, pk2(uv.x, uv.y)); ffma2(p1, ww, pk2(uv.z, uv.w)); }   \
        {   u64 ww = pk2(wv.z, wv.z);                                           \
            float4 uv = *(const float4*)((UIN) + (k + 2) * 8 + bbase);          \
            ffma2(p0, ww, pk2(uv.x, uv.y)); ffma2(p1, ww, pk2(uv.z, uv.w)); }   \
        {   u64 ww = pk2(wv.w, wv.w);                                           \
            float4 uv = *(const float4*)((UIN) + (k + 3) * 8 + bbase);          \
            ffma2(p0, ww, pk2(uv.x, uv.y)); ffma2(p1, ww, pk2(uv.z, uv.w)); }   \
    }                                                                           \
    float a0, a1, a2, a3;                                                       \
    upk2(p0, a0, a1); upk2(p1, a2, a3);                                         \
    float4 hm = *(const float4*)(Hst + (LVL) * 1024 + t * 8 + bbase);           \
    float4 ov;                                                                  \
    ov.x = (hm.x > 0.f) ? a0 : 0.f;                                             \
    ov.y = (hm.y > 0.f) ? a1 : 0.f;                                             \
    ov.z = (hm.z > 0.f) ? a2 : 0.f;                                             \
    ov.w = (hm.w > 0.f) ? a3 : 0.f;                                             \
    *(float4*)((UOUT) + t * 8 + bbase) = ov;                                    \
  } while (0)

__global__ void __launch_bounds__(NTHR)
fused_kernel(const float* __restrict__ centers,
             const float* __restrict__ eps,
             const float* __restrict__ dk,
             const float* __restrict__ Wi,
             const float* __restrict__ Wh,
             const float* __restrict__ bh,
             const float* __restrict__ bf,
             const void* __restrict__ pA2048, const void* __restrict__ pB2048,
             const float* __restrict__ pA128, const float* __restrict__ pB128,
             float* __restrict__ o_res, float* __restrict__ o_fmean,
             float* __restrict__ o_flog, float* __restrict__ o_coeffs,
             float* __restrict__ o_d1c, float* __restrict__ o_d2c,
             float* __restrict__ o_d1o, float* __restrict__ o_d2o,
             float* __restrict__ o_d1f, float* __restrict__ o_d2f)
{
    extern __shared__ float sm[];
    float* Ws   = sm + WS_OFF;
    float* Xst  = sm + XST_OFF;
    float* Hst  = sm + HST_OFF;
    float* Ua   = sm + UA_OFF;
    float* Ub   = sm + UB_OFF;
    float* valP = sm + VALP_OFF;
    float* sS   = sm + SMALL_OFF;
    float* cS   = sS + TB;
    float* xsS  = cS + TB;
    int*   idxS = (int*)(xsS + TB);

    const int tid = threadIdx.x;
    const int half = tid >> 7;
    const int t = tid & 127;
    const int wid = tid >> 5;
    const int lane = tid & 31;
    const int b0 = blockIdx.x * TB;
    const int bbase = half * 4;

    // --- resolve ambiguous inputs ---
    const unsigned* ua_ = (const unsigned*)pA2048;
    bool a_idx = true;
#pragma unroll
    for (int i = 0; i < 8; i++) a_idx &= (ua_[i] < 1000u);
    const int*   idxp = (const int*)(a_idx ? pA2048 : pB2048);
    const float* xsp  = (const float*)(a_idx ? pB2048 : pA2048);
    bool a_bi = true;
#pragma unroll
    for (int i = 0; i < 8; i++) a_bi &= (pA128[i] == 0.0f);
    const float* bi = a_bi ? pA128 : pB128;
    const float* Wf = a_bi ? pB128 : pA128;

    // --- phase 0a ---
    if (tid < TB) {
        int gb = b0 + tid;
        idxS[tid] = idxp[gb];
        cS[tid]   = centers[gb * 4];
        Xst[1 * 8 + tid] = centers[gb * 4 + 1];
        Xst[2 * 8 + tid] = centers[gb * 4 + 2];
        Xst[3 * 8 + tid] = centers[gb * 4 + 3];
        xsS[tid]  = xsp[gb];
    }
    __syncthreads();

    // --- phase 0b: gather feat (transposed), write fmean/flog; stage Wi ---
#pragma unroll
    for (int ii = 0; ii < 4; ii++) {
        int e2 = tid + NTHR * ii;
        int b = e2 >> 7;
        int k = e2 & 127;
        int gb = b0 + b;
        int id = idxS[b];
        float m  = dk[id * 256 + k];
        float ls = dk[id * 256 + 128 + k];
        float ep = eps[id * 128 + k];
        float ft = fmaf(expf(0.5f * ls), ep, m);
        o_fmean[(size_t)gb * 128 + k] = m;
        o_flog[(size_t)gb * 128 + k]  = ls;
        if (k == 0) {
            float s = 1e-10f + expf(-ft);
            sS[b] = s;
            Xst[b] = cS[b] * s;
        } else {
            Xst[(3 + k) * 8 + b] = ft;
        }
    }
    stage_w(Ws, Wi, 131, tid);
    __syncthreads();
    ZCHUNK(0);

    // --- L1 forward (packed) ---
    {
        float bv = bi[t];
        u64 p0 = pk2(bv, bv), p1 = p0;
#pragma unroll 16
        for (int k = 0; k < 128; k++) {
            float w = Ws[k * PITCH + t];
            u64 ww = pk2(w, w);
            float4 hv = *(const float4*)(Xst + k * 8 + bbase);
            ffma2(p0, ww, pk2(hv.x, hv.y));
            ffma2(p1, ww, pk2(hv.z, hv.w));
        }
        float a0, a1, a2, a3;
        upk2(p0, a0, a1); upk2(p1, a2, a3);
#pragma unroll
        for (int i = 0; i < 3; i++) {
            float w = Ws[(128 + i) * PITCH + t];
            a0 = fmaf(Xst[(128 + i) * 8 + bbase + 0], w, a0);
            a1 = fmaf(Xst[(128 + i) * 8 + bbase + 1], w, a1);
            a2 = fmaf(Xst[(128 + i) * 8 + bbase + 2], w, a2);
            a3 = fmaf(Xst[(128 + i) * 8 + bbase + 3], w, a3);
        }
        float4 ov = make_float4(fmaxf(a0, 0.f), fmaxf(a1, 0.f), fmaxf(a2, 0.f), fmaxf(a3, 0.f));
        *(float4*)(Hst + t * 8 + bbase) = ov;
    }
    __syncthreads();
    ZCHUNK(1);

    // --- hidden layers 2..3 (store h2, h3) ---
#pragma unroll
    for (int l = 0; l < 2; l++) {
        stage_w(Ws, Wh + l * 16384, 128, tid);
        __syncthreads();
        float bv = bh[l * 128 + t];
        u64 p0 = pk2(bv, bv), p1 = p0;
        const float* hin = Hst + l * 1024;
#pragma unroll 16
        for (int k = 0; k < 128; k++) {
            float w = Ws[k * PITCH + t];
            u64 ww = pk2(w, w);
            float4 hv = *(const float4*)(hin + k * 8 + bbase);
            ffma2(p0, ww, pk2(hv.x, hv.y));
            ffma2(p1, ww, pk2(hv.z, hv.w));
        }
        float a0, a1, a2, a3;
        upk2(p0, a0, a1); upk2(p1, a2, a3);
        float4 ov = make_float4(fmaxf(a0, 0.f), fmaxf(a1, 0.f), fmaxf(a2, 0.f), fmaxf(a3, 0.f));
        *(float4*)(Hst + (l + 1) * 1024 + t * 8 + bbase) = ov;
        __syncthreads();
        ZCHUNK(2 + l);
    }

    // --- L4 forward + merged val partials + u4 init (h4 never stored) ---
    stage_w(Ws, Wh + 2 * 16384, 128, tid);
    __syncthreads();
    {
        float bv = bh[2 * 128 + t];
        u64 p0 = pk2(bv, bv), p1 = p0;
        const float* hin = Hst + 2 * 1024;
#pragma unroll 16
        for (int k = 0; k < 128; k++) {
            float w = Ws[k * PITCH + t];
            u64 ww = pk2(w, w);
            float4 hv = *(const float4*)(hin + k * 8 + bbase);
            ffma2(p0, ww, pk2(hv.x, hv.y));
            ffma2(p1, ww, pk2(hv.z, hv.w));
        }
        float a0, a1, a2, a3;
        upk2(p0, a0, a1); upk2(p1, a2, a3);

        float wf_t = Wf[t];
        float4 ov;
        ov.x = (a0 > 0.f) ? wf_t : 0.f;
        ov.y = (a1 > 0.f) ? wf_t : 0.f;
        ov.z = (a2 > 0.f) ? wf_t : 0.f;
        ov.w = (a3 > 0.f) ? wf_t : 0.f;
        *(float4*)(Ua + t * 8 + bbase) = ov;

        float q0 = fmaxf(a0, 0.f) * wf_t;
        float q1 = fmaxf(a1, 0.f) * wf_t;
        float q2 = fmaxf(a2, 0.f) * wf_t;
        float q3 = fmaxf(a3, 0.f) * wf_t;
#pragma unroll
        for (int o = 16; o > 0; o >>= 1) {
            q0 += __shfl_down_sync(0xffffffffu, q0, o);
            q1 += __shfl_down_sync(0xffffffffu, q1, o);
            q2 += __shfl_down_sync(0xffffffffu, q2, o);
            q3 += __shfl_down_sync(0xffffffffu, q3, o);
        }
        if (lane == 0) *(float4*)(valP + wid * 4) = make_float4(q0, q1, q2, q3);
    }
    __syncthreads();
    ZCHUNK(4);

    // --- backward chain (Ws holds Wh2 already) ---
    BACKSTEP(Ua, Ub, 2);
    __syncthreads();
    stage_w(Ws, Wh + 1 * 16384, 128, tid);
    __syncthreads();
    BACKSTEP(Ub, Ua, 1);
    __syncthreads();
    ZCHUNK(5);
    stage_w(Ws, Wh + 0 * 16384, 128, tid);
    __syncthreads();
    BACKSTEP(Ua, Ub, 0);
    __syncthreads();
    ZCHUNK(6);
    stage_w(Ws, Wi, 131, tid);
    __syncthreads();

    // --- final: g = Wi @ u1 (packed); outputs; u1 in Ub ---
    {
        u64 p0 = 0ULL, p1 = 0ULL;
#pragma unroll 8
        for (int k = 0; k < 128; k += 4) {
            float4 wv = *(const float4*)(Ws + t * PITCH + k);
            {   u64 ww = pk2(wv.x, wv.x);
                float4 uv = *(const float4*)(Ub + (k + 0) * 8 + bbase);
                ffma2(p0, ww, pk2(uv.x, uv.y)); ffma2(p1, ww, pk2(uv.z, uv.w)); }
            {   u64 ww = pk2(wv.y, wv.y);
                float4 uv = *(const float4*)(Ub + (k + 1) * 8 + bbase);
                ffma2(p0, ww, pk2(uv.x, uv.y)); ffma2(p1, ww, pk2(uv.z, uv.w)); }
            {   u64 ww = pk2(wv.z, wv.z);
                float4 uv = *(const float4*)(Ub + (k + 2) * 8 + bbase);
                ffma2(p0, ww, pk2(uv.x, uv.y)); ffma2(p1, ww, pk2(uv.z, uv.w)); }
            {   u64 ww = pk2(wv.w, wv.w);
                float4 uv = *(const float4*)(Ub + (k + 3) * 8 + bbase);
                ffma2(p0, ww, pk2(uv.x, uv.y)); ffma2(p1, ww, pk2(uv.z, uv.w)); }
        }
        float g[4];
        upk2(p0, g[0], g[1]); upk2(p1, g[2], g[3]);

        if (t >= 4) {
#pragma unroll
            for (int e = 0; e < 4; e++) {
                int gb = b0 + bbase + e;
                o_d1f[(size_t)gb * 128 + (t - 3)] = g[e];
            }
        } else if (t == 0) {
#pragma unroll
            for (int e = 0; e < 4; e++) {
                int bloc = bbase + e;
                int gb = b0 + bloc;
                float val = valP[(half * 4 + 0) * 4 + e] + valP[(half * 4 + 1) * 4 + e]
                          + valP[(half * 4 + 2) * 4 + e] + valP[(half * 4 + 3) * 4 + e]
                          + bf[0];
                float s = sS[bloc], c = cS[bloc];
                float gg = g[e];
                float d1c = gg * s;
                float h00 = gg * c * (s - 1e-10f);   // g0 * c * exp(-ft0)
                o_d1c[gb] = d1c;
                o_d2c[gb] = 0.f;
                o_coeffs[gb] = val;
                o_res[gb] = fmaf(d1c, xsS[bloc] - c, val);
                o_d1f[(size_t)gb * 128] = -h00;
                *(float4*)(o_d2f + (size_t)gb * 16384) = make_float4(h00, 0.f, 0.f, 0.f);
            }
        } else {  // t = 1..3
#pragma unroll
            for (int e = 0; e < 4; e++) {
                int gb = b0 + bbase + e;
                o_d1o[(size_t)gb * 3 + (t - 1)] = g[e];
            }
        }

        // extra Wi rows 128..130 -> d1f[125..127]
        if (t < 3) {
            int r = 128 + t;
            u64 q0 = 0ULL, q1 = 0ULL;
#pragma unroll 8
            for (int k = 0; k < 128; k += 4) {
                float4 wv = *(const float4*)(Ws + r * PITCH + k);
                {   u64 ww = pk2(wv.x, wv.x);
                    float4 uv = *(const float4*)(Ub + (k + 0) * 8 + bbase);
                    ffma2(q0, ww, pk2(uv.x, uv.y)); ffma2(q1, ww, pk2(uv.z, uv.w)); }
                {   u64 ww = pk2(wv.y, wv.y);
                    float4 uv = *(const float4*)(Ub + (k + 1) * 8 + bbase);
                    ffma2(q0, ww, pk2(uv.x, uv.y)); ffma2(q1, ww, pk2(uv.z, uv.w)); }
                {   u64 ww = pk2(wv.z, wv.z);
                    float4 uv = *(const float4*)(Ub + (k + 2) * 8 + bbase);
                    ffma2(q0, ww, pk2(uv.x, uv.y)); ffma2(q1, ww, pk2(uv.z, uv.w)); }
                {   u64 ww = pk2(wv.w, wv.w);
                    float4 uv = *(const float4*)(Ub + (k + 3) * 8 + bbase);
                    ffma2(q0, ww, pk2(uv.x, uv.y)); ffma2(q1, ww, pk2(uv.z, uv.w)); }
            }
            float ge[4];
            upk2(q0, ge[0], ge[1]); upk2(q1, ge[2], ge[3]);
#pragma unroll
            for (int e = 0; e < 4; e++) {
                int gb = b0 + bbase + e;
                o_d1f[(size_t)gb * 128 + 125 + t] = ge[e];
            }
        }

        // d2o zeros
        if (tid < 72) {
            int b = tid / 9, k9 = tid % 9;
            o_d2o[(size_t)(b0 + b) * 9 + k9] = 0.f;
        }
        ZCHUNK(7);
    }
}

extern "C" void kernel_launch(void* const* d_in, const int* in_sizes, int n_in,
                              void* d_out, int out_size)
{
    (void)out_size;
    const float *centers = 0, *eps = 0, *dk = 0, *Wi = 0, *Wh = 0, *bh = 0, *bf = 0;
    const void* p2048[2] = {0, 0};
    const float* p128[2] = {0, 0};
    int n2 = 0, n1 = 0;
    for (int i = 0; i < n_in; i++) {
        switch (in_sizes[i]) {
            case 8192:   centers = (const float*)d_in[i]; break;  // (2048,4)
            case 128000: eps     = (const float*)d_in[i]; break;  // (1000,128)
            case 256000: dk      = (const float*)d_in[i]; break;  // (1000,256)
            case 16768:  Wi      = (const float*)d_in[i]; break;  // (131,128)
            case 49152:  Wh      = (const float*)d_in[i]; break;  // (3,128,128)
            case 384:    bh      = (const float*)d_in[i]; break;  // (3,128)
            case 1:      bf      = (const float*)d_in[i]; break;  // (1,)
            case 2048:   if (n2 < 2) p2048[n2++] = d_in[i]; break; // indecies / xs
            case 128:    if (n1 < 2) p128[n1++] = (const float*)d_in[i]; break; // bi / Wf
            default: break;
        }
    }
    const int B = 2048;
    float* out = (float*)d_out;
    float* o_res    = out;
    float* o_fmean  = out + B;
    float* o_flog   = o_fmean + (size_t)B * 128;
    float* o_coeffs = o_flog + (size_t)B * 128;
    float* o_d1c    = o_coeffs + B;
    float* o_d2c    = o_d1c + B;
    float* o_d1o    = o_d2c + B;
    float* o_d2o    = o_d1o + (size_t)B * 3;
    float* o_d1f    = o_d2o + (size_t)B * 9;
    float* o_d2f    = o_d1f + (size_t)B * 128;

    cudaFuncSetAttribute(fused_kernel, cudaFuncAttributeMaxDynamicSharedMemorySize, SMEM_BYTES);
    fused_kernel<<<NCOMP, NTHR, SMEM_BYTES>>>(
        centers, eps, dk, Wi, Wh, bh, bf,
        p2048[0], p2048[1], p128[0], p128[1],
        o_res, o_fmean, o_flog, o_coeffs, o_d1c, o_d2c, o_d1o, o_d2o, o_d1f, o_d2f);
}

// round 14
// speedup vs baseline: 1.5333x; 1.1089x over previous
#include <cuda_runtime.h>
#include <cstdint>
#include <cstddef>

#define NTHR 128
#define TB 4
#define NBLK 512   // 2048 / TB

// transposed weights in device globals (written by k_tr each launch)
__device__ float gWT[3][16384];     // gWT[l][t*128+k] = Wh[l][k*128+t]
__device__ float gWiT[128 * 132];   // gWiT[t*132+j]   = Wi[j*128+t]  (j<131)

// ---------------------------------------------------------------------------
__global__ void k_tr(const float* __restrict__ Wh, const float* __restrict__ Wi)
{
    int gt = blockIdx.x * 256 + threadIdx.x;
    if (gt < 3 * 16384) {
        int l = gt >> 14, r = gt & 16383, a = r >> 7, b = r & 127;
        gWT[l][r] = Wh[(l << 14) + b * 128 + a];
    } else {
        int g2 = gt - 3 * 16384;
        if (g2 < 128 * 131) {
            int t = g2 / 131, j = g2 % 131;
            gWiT[t * 132 + j] = Wi[j * 128 + t];
        }
    }
}

// zero example e's d2f row (4096 float4), skipping the first float4
#define ZCHUNK(e_) do {                                                         \
    float4 z4 = make_float4(0.f, 0.f, 0.f, 0.f);                                \
    float4* dst_ = (float4*)(o_d2f + (size_t)(b0 + (e_)) * 16384);              \
    for (int i_ = 1 + tid; i_ < 4096; i_ += NTHR) __stcs(dst_ + i_, z4);        \
  } while (0)

// one GEMV step over 128 inputs: out[e] += sum_k Wcol[k*128+t] * act[k*4+e]
#define GEMV128(WCOL, ACT, A0, A1, A2, A3) do {                                 \
    _Pragma("unroll 8")                                                         \
    for (int k = 0; k < 128; k++) {                                             \
        float w = __ldg((WCOL) + k * 128 + t);                                  \
        float4 hv = *(const float4*)((ACT) + k * 4);                            \
        A0 = fmaf(w, hv.x, A0);                                                 \
        A1 = fmaf(w, hv.y, A1);                                                 \
        A2 = fmaf(w, hv.z, A2);                                                 \
        A3 = fmaf(w, hv.w, A3);                                                 \
    }                                                                           \
  } while (0)

__global__ void __launch_bounds__(NTHR)
fused_kernel(const float* __restrict__ centers,
             const float* __restrict__ eps,
             const float* __restrict__ dk,
             const float* __restrict__ Wi,
             const float* __restrict__ Wh,
             const float* __restrict__ bh,
             const float* __restrict__ bf,
             const void* __restrict__ pA2048, const void* __restrict__ pB2048,
             const float* __restrict__ pA128, const float* __restrict__ pB128,
             float* __restrict__ o_res, float* __restrict__ o_fmean,
             float* __restrict__ o_flog, float* __restrict__ o_coeffs,
             float* __restrict__ o_d1c, float* __restrict__ o_d2c,
             float* __restrict__ o_d1o, float* __restrict__ o_d2o,
             float* __restrict__ o_d1f, float* __restrict__ o_d2f)
{
    __shared__ float Xst[528];        // input vectors [k][e], 131 rows
    __shared__ float Hst[3 * 512];    // h1,h2,h3 as [t][e]
    __shared__ float Ua[512];         // backward ping [t][e]
    __shared__ float Ub[512];         // backward pong [t][e]
    __shared__ float valP[16];        // per-warp val partials [w][e]
    __shared__ float sS[TB], cS[TB], xsS[TB];
    __shared__ int   idxS[TB];

    const int tid = threadIdx.x;
    const int t = tid;                 // neuron 0..127
    const int wid = tid >> 5;
    const int lane = tid & 31;
    const int b0 = blockIdx.x * TB;

    // --- resolve ambiguous inputs ---
    const unsigned* ua_ = (const unsigned*)pA2048;
    bool a_idx = true;
#pragma unroll
    for (int i = 0; i < 8; i++) a_idx &= (ua_[i] < 1000u);
    const int*   idxp = (const int*)(a_idx ? pA2048 : pB2048);
    const float* xsp  = (const float*)(a_idx ? pB2048 : pA2048);
    bool a_bi = true;
#pragma unroll
    for (int i = 0; i < 8; i++) a_bi &= (pA128[i] == 0.0f);
    const float* bi = a_bi ? pA128 : pB128;
    const float* Wf = a_bi ? pB128 : pA128;

    // --- phase 0a ---
    if (tid < TB) {
        int gb = b0 + tid;
        idxS[tid] = idxp[gb];
        cS[tid]   = centers[gb * 4];
        Xst[1 * 4 + tid] = centers[gb * 4 + 1];
        Xst[2 * 4 + tid] = centers[gb * 4 + 2];
        Xst[3 * 4 + tid] = centers[gb * 4 + 3];
        xsS[tid]  = xsp[gb];
    }
    __syncthreads();

    // --- phase 0b: gather feat (transposed), write fmean/flog ---
#pragma unroll
    for (int ii = 0; ii < TB; ii++) {
        int e2 = tid + NTHR * ii;
        int b = e2 >> 7;
        int k = e2 & 127;
        int gb = b0 + b;
        int id = idxS[b];
        float m  = dk[id * 256 + k];
        float ls = dk[id * 256 + 128 + k];
        float ep = eps[id * 128 + k];
        float ft = fmaf(expf(0.5f * ls), ep, m);
        o_fmean[(size_t)gb * 128 + k] = m;
        o_flog[(size_t)gb * 128 + k]  = ls;
        if (k == 0) {
            float s = 1e-10f + expf(-ft);
            sS[b] = s;
            Xst[b] = cS[b] * s;
        } else {
            Xst[(3 + k) * 4 + b] = ft;
        }
    }
    __syncthreads();
    ZCHUNK(0);

    // --- L1 forward: h1[t] = relu(sum_j x[j] Wi[j*128+t] + bi[t]) ---
    {
        float bv = bi[t];
        float a0 = bv, a1 = bv, a2 = bv, a3 = bv;
        GEMV128(Wi, Xst, a0, a1, a2, a3);
#pragma unroll
        for (int j = 128; j < 131; j++) {
            float w = __ldg(Wi + j * 128 + t);
            a0 = fmaf(w, Xst[j * 4 + 0], a0);
            a1 = fmaf(w, Xst[j * 4 + 1], a1);
            a2 = fmaf(w, Xst[j * 4 + 2], a2);
            a3 = fmaf(w, Xst[j * 4 + 3], a3);
        }
        *(float4*)(Hst + t * 4) =
            make_float4(fmaxf(a0, 0.f), fmaxf(a1, 0.f), fmaxf(a2, 0.f), fmaxf(a3, 0.f));
    }
    __syncthreads();

    // --- L2, L3 forward ---
#pragma unroll
    for (int l = 0; l < 2; l++) {
        float bv = bh[l * 128 + t];
        float a0 = bv, a1 = bv, a2 = bv, a3 = bv;
        GEMV128(Wh + l * 16384, Hst + l * 512, a0, a1, a2, a3);
        *(float4*)(Hst + (l + 1) * 512 + t * 4) =
            make_float4(fmaxf(a0, 0.f), fmaxf(a1, 0.f), fmaxf(a2, 0.f), fmaxf(a3, 0.f));
        __syncthreads();
        if (l == 0) ZCHUNK(1);
    }

    // --- L4 forward + merged val partials + u4 init (h4 never stored) ---
    {
        float bv = bh[2 * 128 + t];
        float a0 = bv, a1 = bv, a2 = bv, a3 = bv;
        GEMV128(Wh + 2 * 16384, Hst + 2 * 512, a0, a1, a2, a3);

        float wf_t = Wf[t];
        float4 ov;
        ov.x = (a0 > 0.f) ? wf_t : 0.f;
        ov.y = (a1 > 0.f) ? wf_t : 0.f;
        ov.z = (a2 > 0.f) ? wf_t : 0.f;
        ov.w = (a3 > 0.f) ? wf_t : 0.f;
        *(float4*)(Ua + t * 4) = ov;

        float q0 = fmaxf(a0, 0.f) * wf_t;
        float q1 = fmaxf(a1, 0.f) * wf_t;
        float q2 = fmaxf(a2, 0.f) * wf_t;
        float q3 = fmaxf(a3, 0.f) * wf_t;
#pragma unroll
        for (int o = 16; o > 0; o >>= 1) {
            q0 += __shfl_down_sync(0xffffffffu, q0, o);
            q1 += __shfl_down_sync(0xffffffffu, q1, o);
            q2 += __shfl_down_sync(0xffffffffu, q2, o);
            q3 += __shfl_down_sync(0xffffffffu, q3, o);
        }
        if (lane == 0) *(float4*)(valP + wid * 4) = make_float4(q0, q1, q2, q3);
    }
    __syncthreads();
    ZCHUNK(2);

    // --- backward chain: coalesced transposed-weight columns ---
    // B3: u3 = D3 (Wh2^T u4)
    {
        float a0 = 0.f, a1 = 0.f, a2 = 0.f, a3 = 0.f;
        GEMV128(gWT[2], Ua, a0, a1, a2, a3);
        float4 hm = *(const float4*)(Hst + 2 * 512 + t * 4);
        float4 ov;
        ov.x = (hm.x > 0.f) ? a0 : 0.f;
        ov.y = (hm.y > 0.f) ? a1 : 0.f;
        ov.z = (hm.z > 0.f) ? a2 : 0.f;
        ov.w = (hm.w > 0.f) ? a3 : 0.f;
        *(float4*)(Ub + t * 4) = ov;
    }
    __syncthreads();
    // B2
    {
        float a0 = 0.f, a1 = 0.f, a2 = 0.f, a3 = 0.f;
        GEMV128(gWT[1], Ub, a0, a1, a2, a3);
        float4 hm = *(const float4*)(Hst + 1 * 512 + t * 4);
        float4 ov;
        ov.x = (hm.x > 0.f) ? a0 : 0.f;
        ov.y = (hm.y > 0.f) ? a1 : 0.f;
        ov.z = (hm.z > 0.f) ? a2 : 0.f;
        ov.w = (hm.w > 0.f) ? a3 : 0.f;
        *(float4*)(Ua + t * 4) = ov;
    }
    __syncthreads();
    ZCHUNK(3);
    // B1
    {
        float a0 = 0.f, a1 = 0.f, a2 = 0.f, a3 = 0.f;
        GEMV128(gWT[0], Ua, a0, a1, a2, a3);
        float4 hm = *(const float4*)(Hst + 0 * 512 + t * 4);
        float4 ov;
        ov.x = (hm.x > 0.f) ? a0 : 0.f;
        ov.y = (hm.y > 0.f) ? a1 : 0.f;
        ov.z = (hm.z > 0.f) ? a2 : 0.f;
        ov.w = (hm.w > 0.f) ? a3 : 0.f;
        *(float4*)(Ub + t * 4) = ov;
    }
    __syncthreads();

    // --- final: g[j] = sum_t WiT[t*132+j] * u1[t]; u1 in Ub ---
    {
        float g0 = 0.f, g1 = 0.f, g2 = 0.f, g3 = 0.f;
        int j = t;
#pragma unroll 8
        for (int k = 0; k < 128; k++) {
            float w = __ldg(gWiT + k * 132 + j);
            float4 uv = *(const float4*)(Ub + k * 4);
            g0 = fmaf(w, uv.x, g0);
            g1 = fmaf(w, uv.y, g1);
            g2 = fmaf(w, uv.z, g2);
            g3 = fmaf(w, uv.w, g3);
        }
        float g[4] = {g0, g1, g2, g3};

        if (j >= 4) {
#pragma unroll
            for (int e = 0; e < TB; e++) {
                int gb = b0 + e;
                o_d1f[(size_t)gb * 128 + (j - 3)] = g[e];
            }
        } else if (j == 0) {
#pragma unroll
            for (int e = 0; e < TB; e++) {
                int gb = b0 + e;
                float val = valP[0 * 4 + e] + valP[1 * 4 + e]
                          + valP[2 * 4 + e] + valP[3 * 4 + e] + bf[0];
                float s = sS[e], c = cS[e];
                float gg = g[e];
                float d1c = gg * s;
                float h00 = gg * c * (s - 1e-10f);   // g0 * c * exp(-ft0)
                o_d1c[gb] = d1c;
                o_d2c[gb] = 0.f;
                o_coeffs[gb] = val;
                o_res[gb] = fmaf(d1c, xsS[e] - c, val);
                o_d1f[(size_t)gb * 128] = -h00;
                *(float4*)(o_d2f + (size_t)gb * 16384) = make_float4(h00, 0.f, 0.f, 0.f);
            }
        } else {  // j = 1..3
#pragma unroll
            for (int e = 0; e < TB; e++) {
                int gb = b0 + e;
                o_d1o[(size_t)gb * 3 + (j - 1)] = g[e];
            }
        }

        // extra input rows j=128..130 -> d1f[125..127]
        if (t < 3) {
            int j2 = 128 + t;
            float q0 = 0.f, q1 = 0.f, q2 = 0.f, q3 = 0.f;
#pragma unroll 8
            for (int k = 0; k < 128; k++) {
                float w = __ldg(gWiT + k * 132 + j2);
                float4 uv = *(const float4*)(Ub + k * 4);
                q0 = fmaf(w, uv.x, q0);
                q1 = fmaf(w, uv.y, q1);
                q2 = fmaf(w, uv.z, q2);
                q3 = fmaf(w, uv.w, q3);
            }
            float qe[4] = {q0, q1, q2, q3};
#pragma unroll
            for (int e = 0; e < TB; e++) {
                int gb = b0 + e;
                o_d1f[(size_t)gb * 128 + 125 + t] = qe[e];
            }
        }

        // d2o zeros (4 examples x 9)
        if (tid < TB * 9) {
            int b = tid / 9, k9 = tid % 9;
            o_d2o[(size_t)(b0 + b) * 9 + k9] = 0.f;
        }
    }
}

extern "C" void kernel_launch(void* const* d_in, const int* in_sizes, int n_in,
                              void* d_out, int out_size)
{
    (void)out_size;
    const float *centers = 0, *eps = 0, *dk = 0, *Wi = 0, *Wh = 0, *bh = 0, *bf = 0;
    const void* p2048[2] = {0, 0};
    const float* p128[2] = {0, 0};
    int n2 = 0, n1 = 0;
    for (int i = 0; i < n_in; i++) {
        switch (in_sizes[i]) {
            case 8192:   centers = (const float*)d_in[i]; break;  // (2048,4)
            case 128000: eps     = (const float*)d_in[i]; break;  // (1000,128)
            case 256000: dk      = (const float*)d_in[i]; break;  // (1000,256)
            case 16768:  Wi      = (const float*)d_in[i]; break;  // (131,128)
            case 49152:  Wh      = (const float*)d_in[i]; break;  // (3,128,128)
            case 384:    bh      = (const float*)d_in[i]; break;  // (3,128)
            case 1:      bf      = (const float*)d_in[i]; break;  // (1,)
            case 2048:   if (n2 < 2) p2048[n2++] = d_in[i]; break; // indecies / xs
            case 128:    if (n1 < 2) p128[n1++] = (const float*)d_in[i]; break; // bi / Wf
            default: break;
        }
    }
    const int B = 2048;
    float* out = (float*)d_out;
    float* o_res    = out;
    float* o_fmean  = out + B;
    float* o_flog   = o_fmean + (size_t)B * 128;
    float* o_coeffs = o_flog + (size_t)B * 128;
    float* o_d1c    = o_coeffs + B;
    float* o_d2c    = o_d1c + B;
    float* o_d1o    = o_d2c + B;
    float* o_d2o    = o_d1o + (size_t)B * 3;
    float* o_d1f    = o_d2o + (size_t)B * 9;
    float* o_d2f    = o_d1f + (size_t)B * 128;

    k_tr<<<258, 256>>>(Wh, Wi);
    fused_kernel<<<NBLK, NTHR>>>(
        centers, eps, dk, Wi, Wh, bh, bf,
        p2048[0], p2048[1], p128[0], p128[1],
        o_res, o_fmean, o_flog, o_coeffs, o_d1c, o_d2c, o_d1o, o_d2o, o_d1f, o_d2f);
}

// round 15
// speedup vs baseline: 1.5905x; 1.0373x over previous
#include <cuda_runtime.h>
#include <cstdint>
#include <cstddef>

#define NTHR 256
#define TB 4
#define NBLK 512   // 2048 / TB

// transposed weights in device globals (written by k_tr each launch)
__device__ float gWT[3][16384];     // gWT[l][t*128+k] = Wh[l][k*128+t]
__device__ float gWiT[128 * 132];   // gWiT[t*132+j]   = Wi[j*128+t]  (j<131)

__global__ void k_tr(const float* __restrict__ Wh, const float* __restrict__ Wi)
{
    int gt = blockIdx.x * 256 + threadIdx.x;
    if (gt < 3 * 16384) {
        int l = gt >> 14, r = gt & 16383, a = r >> 7, b = r & 127;
        gWT[l][r] = Wh[(l << 14) + b * 128 + a];
    } else {
        int g2 = gt - 3 * 16384;
        if (g2 < 128 * 131) {
            int t = g2 / 131, j = g2 % 131;
            gWiT[t * 132 + j] = Wi[j * 128 + t];
        }
    }
}

// zero example e's d2f row (4096 float4), skipping the first float4
#define ZCHUNK(e_) do {                                                         \
    float4 z4 = make_float4(0.f, 0.f, 0.f, 0.f);                                \
    float4* dst_ = (float4*)(o_d2f + (size_t)(b0 + (e_)) * 16384);              \
    for (int i_ = 1 + tid; i_ < 4096; i_ += NTHR) __stcs(dst_ + i_, z4);        \
  } while (0)

// split-K partial GEMV: acc over k in [K0,K1)
#define GEMVPART(WCOL, PITCHW, ACT, K0, K1, A0, A1, A2, A3) do {                \
    _Pragma("unroll 8")                                                         \
    for (int k = (K0); k < (K1); k++) {                                         \
        float w = __ldg((WCOL) + k * (PITCHW) + t);                             \
        float4 hv = *(const float4*)((ACT) + k * 4);                            \
        A0 = fmaf(w, hv.x, A0);                                                 \
        A1 = fmaf(w, hv.y, A1);                                                 \
        A2 = fmaf(w, hv.z, A2);                                                 \
        A3 = fmaf(w, hv.w, A3);                                                 \
    }                                                                           \
  } while (0)

__global__ void __launch_bounds__(NTHR)
fused_kernel(const float* __restrict__ centers,
             const float* __restrict__ eps,
             const float* __restrict__ dk,
             const float* __restrict__ Wi,
             const float* __restrict__ Wh,
             const float* __restrict__ bh,
             const float* __restrict__ bf,
             const void* __restrict__ pA2048, const void* __restrict__ pB2048,
             const float* __restrict__ pA128, const float* __restrict__ pB128,
             float* __restrict__ o_res, float* __restrict__ o_fmean,
             float* __restrict__ o_flog, float* __restrict__ o_coeffs,
             float* __restrict__ o_d1c, float* __restrict__ o_d2c,
             float* __restrict__ o_d1o, float* __restrict__ o_d2o,
             float* __restrict__ o_d1f, float* __restrict__ o_d2f)
{
    __shared__ float Xst[528];        // input vectors [k][e], 131 rows
    __shared__ float Hst[3 * 512];    // h1,h2,h3 as [t][e]  (relu'd, = masks)
    __shared__ float Ua[512];         // backward ping [t][e]
    __shared__ float Ub[512];         // backward pong [t][e]
    __shared__ float Ps[2 * 512];     // split-K partials [kh][t][e]
    __shared__ float valP[16];        // per-warp val partials [w][e]
    __shared__ float sS[TB], cS[TB], xsS[TB];
    __shared__ int   idxS[TB];

    const int tid = threadIdx.x;
    const int t  = tid & 127;          // neuron / output index
    const int kh = tid >> 7;           // k-half 0/1
    const int wid = tid >> 5;
    const int lane = tid & 31;
    const int b0 = blockIdx.x * TB;

    // --- resolve ambiguous inputs ---
    const unsigned* ua_ = (const unsigned*)pA2048;
    bool a_idx = true;
#pragma unroll
    for (int i = 0; i < 8; i++) a_idx &= (ua_[i] < 1000u);
    const int*   idxp = (const int*)(a_idx ? pA2048 : pB2048);
    const float* xsp  = (const float*)(a_idx ? pB2048 : pA2048);
    bool a_bi = true;
#pragma unroll
    for (int i = 0; i < 8; i++) a_bi &= (pA128[i] == 0.0f);
    const float* bi = a_bi ? pA128 : pB128;
    const float* Wf = a_bi ? pB128 : pA128;

    // --- phase 0a ---
    if (tid < TB) {
        int gb = b0 + tid;
        idxS[tid] = idxp[gb];
        cS[tid]   = centers[gb * 4];
        Xst[1 * 4 + tid] = centers[gb * 4 + 1];
        Xst[2 * 4 + tid] = centers[gb * 4 + 2];
        Xst[3 * 4 + tid] = centers[gb * 4 + 3];
        xsS[tid]  = xsp[gb];
    }
    __syncthreads();

    // --- phase 0b: gather feat (transposed), write fmean/flog ---
#pragma unroll
    for (int ii = 0; ii < 2; ii++) {
        int e2 = tid + NTHR * ii;
        int b = e2 >> 7;
        int k = e2 & 127;
        int gb = b0 + b;
        int id = idxS[b];
        float m  = dk[id * 256 + k];
        float ls = dk[id * 256 + 128 + k];
        float ep = eps[id * 128 + k];
        float ft = fmaf(expf(0.5f * ls), ep, m);
        o_fmean[(size_t)gb * 128 + k] = m;
        o_flog[(size_t)gb * 128 + k]  = ls;
        if (k == 0) {
            float s = 1e-10f + expf(-ft);
            sS[b] = s;
            Xst[b] = cS[b] * s;
        } else {
            Xst[(3 + k) * 4 + b] = ft;
        }
    }
    __syncthreads();
    ZCHUNK(0);

    // --- L1: partial over j in [0,66) / [66,131) ---
    {
        float a0, a1, a2, a3;
        if (kh == 0) { float bv = bi[t]; a0 = a1 = a2 = a3 = bv; }
        else         { a0 = a1 = a2 = a3 = 0.f; }
        int j0 = kh ? 66 : 0, j1 = kh ? 131 : 66;
        GEMVPART(Wi, 128, Xst, j0, j1, a0, a1, a2, a3);
        *(float4*)(Ps + kh * 512 + t * 4) = make_float4(a0, a1, a2, a3);
    }
    __syncthreads();
    if (kh == 0) {
        float4 p0 = *(const float4*)(Ps + t * 4);
        float4 p1 = *(const float4*)(Ps + 512 + t * 4);
        *(float4*)(Hst + t * 4) = make_float4(
            fmaxf(p0.x + p1.x, 0.f), fmaxf(p0.y + p1.y, 0.f),
            fmaxf(p0.z + p1.z, 0.f), fmaxf(p0.w + p1.w, 0.f));
    }
    __syncthreads();

    // --- L2, L3 ---
#pragma unroll
    for (int l = 0; l < 2; l++) {
        float a0, a1, a2, a3;
        if (kh == 0) { float bv = bh[l * 128 + t]; a0 = a1 = a2 = a3 = bv; }
        else         { a0 = a1 = a2 = a3 = 0.f; }
        GEMVPART(Wh + l * 16384, 128, Hst + l * 512, kh * 64, kh * 64 + 64, a0, a1, a2, a3);
        *(float4*)(Ps + kh * 512 + t * 4) = make_float4(a0, a1, a2, a3);
        __syncthreads();
        if (kh == 0) {
            float4 p0 = *(const float4*)(Ps + t * 4);
            float4 p1 = *(const float4*)(Ps + 512 + t * 4);
            *(float4*)(Hst + (l + 1) * 512 + t * 4) = make_float4(
                fmaxf(p0.x + p1.x, 0.f), fmaxf(p0.y + p1.y, 0.f),
                fmaxf(p0.z + p1.z, 0.f), fmaxf(p0.w + p1.w, 0.f));
        }
        __syncthreads();
        if (l == 0) ZCHUNK(1);
    }

    // --- L4 + val partials + u4 init (h4 never stored) ---
    {
        float a0, a1, a2, a3;
        if (kh == 0) { float bv = bh[2 * 128 + t]; a0 = a1 = a2 = a3 = bv; }
        else         { a0 = a1 = a2 = a3 = 0.f; }
        GEMVPART(Wh + 2 * 16384, 128, Hst + 2 * 512, kh * 64, kh * 64 + 64, a0, a1, a2, a3);
        *(float4*)(Ps + kh * 512 + t * 4) = make_float4(a0, a1, a2, a3);
    }
    __syncthreads();
    if (kh == 0) {
        float4 p0 = *(const float4*)(Ps + t * 4);
        float4 p1 = *(const float4*)(Ps + 512 + t * 4);
        float a0 = p0.x + p1.x, a1 = p0.y + p1.y, a2 = p0.z + p1.z, a3 = p0.w + p1.w;
        float wf_t = Wf[t];
        float4 ov;
        ov.x = (a0 > 0.f) ? wf_t : 0.f;
        ov.y = (a1 > 0.f) ? wf_t : 0.f;
        ov.z = (a2 > 0.f) ? wf_t : 0.f;
        ov.w = (a3 > 0.f) ? wf_t : 0.f;
        *(float4*)(Ua + t * 4) = ov;

        float q0 = fmaxf(a0, 0.f) * wf_t;
        float q1 = fmaxf(a1, 0.f) * wf_t;
        float q2 = fmaxf(a2, 0.f) * wf_t;
        float q3 = fmaxf(a3, 0.f) * wf_t;
#pragma unroll
        for (int o = 16; o > 0; o >>= 1) {
            q0 += __shfl_down_sync(0xffffffffu, q0, o);
            q1 += __shfl_down_sync(0xffffffffu, q1, o);
            q2 += __shfl_down_sync(0xffffffffu, q2, o);
            q3 += __shfl_down_sync(0xffffffffu, q3, o);
        }
        if (lane == 0) *(float4*)(valP + wid * 4) = make_float4(q0, q1, q2, q3);
    }
    __syncthreads();
    ZCHUNK(2);

    // --- backward: B3 (Wh2^T), B2 (Wh1^T), B1 (Wh0^T) — split-K partials ---
#pragma unroll
    for (int s = 0; s < 3; s++) {
        const float* WT = gWT[2 - s];
        const float* Uin  = (s == 1) ? Ub : Ua;   // B3: Ua->Ub, B2: Ub->Ua, B1: Ua->Ub
        float*       Uout = (s == 1) ? Ua : Ub;
        const float* Hm = Hst + (2 - s) * 512;
        float a0 = 0.f, a1 = 0.f, a2 = 0.f, a3 = 0.f;
        GEMVPART(WT, 128, Uin, kh * 64, kh * 64 + 64, a0, a1, a2, a3);
        *(float4*)(Ps + kh * 512 + t * 4) = make_float4(a0, a1, a2, a3);
        __syncthreads();
        if (kh == 0) {
            float4 p0 = *(const float4*)(Ps + t * 4);
            float4 p1 = *(const float4*)(Ps + 512 + t * 4);
            float4 hm = *(const float4*)(Hm + t * 4);
            float4 ov;
            ov.x = (hm.x > 0.f) ? (p0.x + p1.x) : 0.f;
            ov.y = (hm.y > 0.f) ? (p0.y + p1.y) : 0.f;
            ov.z = (hm.z > 0.f) ? (p0.z + p1.z) : 0.f;
            ov.w = (hm.w > 0.f) ? (p0.w + p1.w) : 0.f;
            *(float4*)(Uout + t * 4) = ov;
        }
        __syncthreads();
        if (s == 0) ZCHUNK(3);
    }

    // --- final: g[j] = sum_k WiT[k*132+j] * u1[k]; u1 in Ub ---
    {
        int j = t;
        float g0 = 0.f, g1 = 0.f, g2 = 0.f, g3 = 0.f;
#pragma unroll 8
        for (int k = kh * 64; k < kh * 64 + 64; k++) {
            float w = __ldg(gWiT + k * 132 + j);
            float4 uv = *(const float4*)(Ub + k * 4);
            g0 = fmaf(w, uv.x, g0);
            g1 = fmaf(w, uv.y, g1);
            g2 = fmaf(w, uv.z, g2);
            g3 = fmaf(w, uv.w, g3);
        }
        *(float4*)(Ps + kh * 512 + t * 4) = make_float4(g0, g1, g2, g3);
    }
    __syncthreads();

    if (kh == 0) {
        int j = t;
        float4 p0 = *(const float4*)(Ps + t * 4);
        float4 p1 = *(const float4*)(Ps + 512 + t * 4);
        float g[4] = {p0.x + p1.x, p0.y + p1.y, p0.z + p1.z, p0.w + p1.w};

        if (j >= 4) {
#pragma unroll
            for (int e = 0; e < TB; e++) {
                int gb = b0 + e;
                o_d1f[(size_t)gb * 128 + (j - 3)] = g[e];
            }
        } else if (j == 0) {
#pragma unroll
            for (int e = 0; e < TB; e++) {
                int gb = b0 + e;
                float val = valP[0 * 4 + e] + valP[1 * 4 + e]
                          + valP[2 * 4 + e] + valP[3 * 4 + e] + bf[0];
                float s = sS[e], c = cS[e];
                float gg = g[e];
                float d1c = gg * s;
                float h00 = gg * c * (s - 1e-10f);   // g0 * c * exp(-ft0)
                o_d1c[gb] = d1c;
                o_d2c[gb] = 0.f;
                o_coeffs[gb] = val;
                o_res[gb] = fmaf(d1c, xsS[e] - c, val);
                o_d1f[(size_t)gb * 128] = -h00;
                *(float4*)(o_d2f + (size_t)gb * 16384) = make_float4(h00, 0.f, 0.f, 0.f);
            }
        } else {  // j = 1..3
#pragma unroll
            for (int e = 0; e < TB; e++) {
                int gb = b0 + e;
                o_d1o[(size_t)gb * 3 + (j - 1)] = g[e];
            }
        }
    } else if (t < 3) {
        // extra input rows j=128..130 -> d1f[125..127], done by half-1 in parallel
        int j2 = 128 + t;
        float q0 = 0.f, q1 = 0.f, q2 = 0.f, q3 = 0.f;
#pragma unroll 8
        for (int k = 0; k < 128; k++) {
            float w = __ldg(gWiT + k * 132 + j2);
            float4 uv = *(const float4*)(Ub + k * 4);
            q0 = fmaf(w, uv.x, q0);
            q1 = fmaf(w, uv.y, q1);
            q2 = fmaf(w, uv.z, q2);
            q3 = fmaf(w, uv.w, q3);
        }
        float qe[4] = {q0, q1, q2, q3};
#pragma unroll
        for (int e = 0; e < TB; e++) {
            int gb = b0 + e;
            o_d1f[(size_t)gb * 128 + 125 + t] = qe[e];
        }
    }

    // d2o zeros (4 examples x 9)
    if (tid >= 128 && tid < 128 + TB * 9) {
        int r = tid - 128;
        int b = r / 9, k9 = r % 9;
        o_d2o[(size_t)(b0 + b) * 9 + k9] = 0.f;
    }
}

extern "C" void kernel_launch(void* const* d_in, const int* in_sizes, int n_in,
                              void* d_out, int out_size)
{
    (void)out_size;
    const float *centers = 0, *eps = 0, *dk = 0, *Wi = 0, *Wh = 0, *bh = 0, *bf = 0;
    const void* p2048[2] = {0, 0};
    const float* p128[2] = {0, 0};
    int n2 = 0, n1 = 0;
    for (int i = 0; i < n_in; i++) {
        switch (in_sizes[i]) {
            case 8192:   centers = (const float*)d_in[i]; break;  // (2048,4)
            case 128000: eps     = (const float*)d_in[i]; break;  // (1000,128)
            case 256000: dk      = (const float*)d_in[i]; break;  // (1000,256)
            case 16768:  Wi      = (const float*)d_in[i]; break;  // (131,128)
            case 49152:  Wh      = (const float*)d_in[i]; break;  // (3,128,128)
            case 384:    bh      = (const float*)d_in[i]; break;  // (3,128)
            case 1:      bf      = (const float*)d_in[i]; break;  // (1,)
            case 2048:   if (n2 < 2) p2048[n2++] = d_in[i]; break; // indecies / xs
            case 128:    if (n1 < 2) p128[n1++] = (const float*)d_in[i]; break; // bi / Wf
            default: break;
        }
    }
    const int B = 2048;
    float* out = (float*)d_out;
    float* o_res    = out;
    float* o_fmean  = out + B;
    float* o_flog   = o_fmean + (size_t)B * 128;
    float* o_coeffs = o_flog + (size_t)B * 128;
    float* o_d1c    = o_coeffs + B;
    float* o_d2c    = o_d1c + B;
    float* o_d1o    = o_d2c + B;
    float* o_d2o    = o_d1o + (size_t)B * 3;
    float* o_d1f    = o_d2o + (size_t)B * 9;
    float* o_d2f    = o_d1f + (size_t)B * 128;

    k_tr<<<258, 256>>>(Wh, Wi);
    fused_kernel<<<NBLK, NTHR>>>(
        centers, eps, dk, Wi, Wh, bh, bf,
        p2048[0], p2048[1], p128[0], p128[1],
        o_res, o_fmean, o_flog, o_coeffs, o_d1c, o_d2c, o_d1o, o_d2o, o_d1f, o_d2f);
}